// round 13
// baseline (speedup 1.0000x reference)
#include <cuda_runtime.h>
#include <cuda_fp16.h>
#include <cstdint>

#define BATCH 2
#define DIM   128
#define HS    62
#define HX    248
#define PS_S  (HS*HS)   // 3844
#define PS_X  (HX*HX)   // 61504
#define NWIN  100       // 10x10 windows
#define NPART (BATCH*NWIN*4)   // 800 (bn,h) pairs

// ---------------- scratch ----------------------------------------------------
__device__ __half   g_xp  [BATCH*DIM*PS_X];
__device__ __half   g_spp [BATCH*DIM*PS_S];
__device__ __half   g_tkv [BATCH*2*DIM*PS_X];
__device__ __half   g_tq  [BATCH*DIM*PS_S];
__device__ uint32_t g_ki  [BATCH*64*PS_X];      // K fp16, ch-pair interleaved
__device__ __half   g_v   [BATCH*DIM*PS_X];     // V fp16, plain planes
__device__ uint32_t g_qi  [BATCH*64*PS_S];      // Q fp16, ch-pair interleaved
__device__ float    g_pO  [2*NPART*64*32];      // split-K partial O
__device__ float    g_pm  [2*NPART*64];
__device__ float    g_pl  [2*NPART*64];
__device__ float    g_win [BATCH*NWIN*DIM*64];
__device__ float    g_acc [BATCH*DIM*PS_S];
__device__ float    g_wq_t  [DIM*DIM];
__device__ float    g_wkv_t [DIM*2*DIM];
__device__ float    g_wout_t[DIM*DIM];

__device__ __forceinline__ uint32_t f2tf32(float f) {
    uint32_t u;
    asm("cvt.rna.tf32.f32 %0, %1;" : "=r"(u) : "f"(f));
    return u;
}
__device__ __forceinline__ float ex2(float x) {
    float y;
    asm("ex2.approx.f32 %0, %1;" : "=f"(y) : "f"(x));
    return y;
}
__device__ __forceinline__ uint32_t h2pack(float lo, float hi) {
    __half2 hh = __floats2half2_rn(lo, hi);
    return *reinterpret_cast<uint32_t*>(&hh);
}

#define MMA_TF32(C0,C1,C2,C3,A0,A1,A2,A3,B0,B1)                               \
    asm volatile(                                                             \
        "mma.sync.aligned.m16n8k8.row.col.f32.tf32.tf32.f32 "                 \
        "{%0,%1,%2,%3}, {%4,%5,%6,%7}, {%8,%9}, {%0,%1,%2,%3};"               \
        : "+f"(C0), "+f"(C1), "+f"(C2), "+f"(C3)                              \
        : "r"(A0), "r"(A1), "r"(A2), "r"(A3), "r"(B0), "r"(B1))

#define MMA_F16(C0,C1,C2,C3,A0,A1,A2,A3,B0,B1)                                \
    asm volatile(                                                             \
        "mma.sync.aligned.m16n8k16.row.col.f32.f16.f16.f32 "                  \
        "{%0,%1,%2,%3}, {%4,%5,%6,%7}, {%8,%9}, {%0,%1,%2,%3};"               \
        : "+f"(C0), "+f"(C1), "+f"(C2), "+f"(C3)                              \
        : "r"(A0), "r"(A1), "r"(A2), "r"(A3), "r"(B0), "r"(B1))

__device__ __forceinline__ void cp16(uint32_t dst, const void* src) {
    asm volatile("cp.async.cg.shared.global [%0], [%1], 16;" :: "r"(dst), "l"(src));
}

// ---------------- all weight transposes in one kernel ------------------------
__global__ void transpose_all(const float* __restrict__ wq,
                              const float* __restrict__ wkv,
                              const float* __restrict__ wout,
                              float* __restrict__ wqt,
                              float* __restrict__ wkvt,
                              float* __restrict__ woutt, float scale) {
    int idx = blockIdx.x * 256 + threadIdx.x;
    if (idx < 16384) {
        int o = idx >> 7, c = idx & 127;
        wqt[c * 128 + o] = wq[idx] * scale;
    } else if (idx < 49152) {
        int i = idx - 16384;
        int o = i >> 7, c = i & 127;
        wkvt[c * 256 + o] = wkv[i];
    } else if (idx < 65536) {
        int i = idx - 49152;
        int o = i >> 7, c = i & 127;
        woutt[c * 128 + o] = wout[i];
    }
}

// ---------------- depthwise 3x3 compute, fp32 input --------------------------
__device__ __forceinline__ bool dw3_compute(const float* __restrict__ ip,
                                            int H, int W,
                                            const float* __restrict__ wc,
                                            float centerAdd, float binit,
                                            bool vec, int y0, int x0,
                                            float acc[4][4]) {
    float w0[3] = {wc[0], wc[3], wc[6]};
    float w1[3] = {wc[1], wc[4] + centerAdd, wc[7]};
    float w2[3] = {wc[2], wc[5], wc[8]};
#pragma unroll
    for (int r = 0; r < 4; r++)
#pragma unroll
        for (int j = 0; j < 4; j++) acc[r][j] = binit;

    bool fast = vec && (x0 >= 4) && (x0 + 8 <= W) && (y0 >= 1) && (y0 + 5 <= H);

    if (fast) {
#pragma unroll
        for (int iy = 0; iy < 6; iy++) {
            const float* rp = ip + (size_t)(y0 + iy - 1) * W;
            float4 mid = *(const float4*)(rp + x0);
            float v[6] = {rp[x0 - 1], mid.x, mid.y, mid.z, mid.w, rp[x0 + 4]};
#pragma unroll
            for (int r = 0; r < 4; r++) {
                int k = iy - r;
                if (k < 0 || k > 2) continue;
                float wy0 = w0[k], wy1 = w1[k], wy2 = w2[k];
#pragma unroll
                for (int j = 0; j < 4; j++)
                    acc[r][j] += v[j] * wy0 + v[j + 1] * wy1 + v[j + 2] * wy2;
            }
        }
    } else {
#pragma unroll
        for (int iy = 0; iy < 6; iy++) {
            int yy = y0 + iy - 1;
            if ((unsigned)yy >= (unsigned)H) continue;
            const float* rp = ip + (size_t)yy * W;
            float v[6];
#pragma unroll
            for (int i = 0; i < 6; i++) {
                int xx = x0 - 1 + i;
                v[i] = ((unsigned)xx < (unsigned)W) ? rp[xx] : 0.0f;
            }
#pragma unroll
            for (int r = 0; r < 4; r++) {
                int k = iy - r;
                if (k < 0 || k > 2) continue;
                float wy0 = w0[k], wy1 = w1[k], wy2 = w2[k];
#pragma unroll
                for (int j = 0; j < 4; j++)
                    acc[r][j] += v[j] * wy0 + v[j + 1] * wy1 + v[j + 2] * wy2;
            }
        }
    }
    return fast;
}

// ---------------- depthwise 3x3 compute, fp16 input --------------------------
__device__ __forceinline__ bool dw3_compute_h(const __half* __restrict__ ip,
                                              int H, int W,
                                              const float* __restrict__ wc,
                                              bool vec, int y0, int x0,
                                              float acc[4][4]) {
    float w0[3] = {wc[0], wc[3], wc[6]};
    float w1[3] = {wc[1], wc[4], wc[7]};
    float w2[3] = {wc[2], wc[5], wc[8]};
#pragma unroll
    for (int r = 0; r < 4; r++)
#pragma unroll
        for (int j = 0; j < 4; j++) acc[r][j] = 0.0f;

    bool fast = vec && (x0 >= 4) && (x0 + 8 <= W) && (y0 >= 1) && (y0 + 5 <= H);

    if (fast) {
#pragma unroll
        for (int iy = 0; iy < 6; iy++) {
            const __half* rp = ip + (size_t)(y0 + iy - 1) * W;
            uint2 m = *(const uint2*)(rp + x0);
            __half2 m01 = *reinterpret_cast<__half2*>(&m.x);
            __half2 m23 = *reinterpret_cast<__half2*>(&m.y);
            float2 f01 = __half22float2(m01);
            float2 f23 = __half22float2(m23);
            float v[6] = {__half2float(rp[x0 - 1]), f01.x, f01.y,
                          f23.x, f23.y, __half2float(rp[x0 + 4])};
#pragma unroll
            for (int r = 0; r < 4; r++) {
                int k = iy - r;
                if (k < 0 || k > 2) continue;
                float wy0 = w0[k], wy1 = w1[k], wy2 = w2[k];
#pragma unroll
                for (int j = 0; j < 4; j++)
                    acc[r][j] += v[j] * wy0 + v[j + 1] * wy1 + v[j + 2] * wy2;
            }
        }
    } else {
#pragma unroll
        for (int iy = 0; iy < 6; iy++) {
            int yy = y0 + iy - 1;
            if ((unsigned)yy >= (unsigned)H) continue;
            const __half* rp = ip + (size_t)yy * W;
            float v[6];
#pragma unroll
            for (int i = 0; i < 6; i++) {
                int xx = x0 - 1 + i;
                v[i] = ((unsigned)xx < (unsigned)W) ? __half2float(rp[xx]) : 0.0f;
            }
#pragma unroll
            for (int r = 0; r < 4; r++) {
                int k = iy - r;
                if (k < 0 || k > 2) continue;
                float wy0 = w0[k], wy1 = w1[k], wy2 = w2[k];
#pragma unroll
                for (int j = 0; j < 4; j++)
                    acc[r][j] += v[j] * wy0 + v[j + 1] * wy1 + v[j + 2] * wy2;
            }
        }
    }
    return fast;
}

// ---------------- pos dw3 uber (fp16 out) ------------------------------------
__global__ void dw3_pos_uber(const float* __restrict__ x, __half* __restrict__ xp,
                             const float* __restrict__ sp, __half* __restrict__ spp,
                             const float* __restrict__ w, const float* __restrict__ bias) {
    int py = blockIdx.y;
    const float* in; __half* out; int H, W; bool vec;
    int plane;
    if (py < BATCH * DIM) { plane = py; in = x; out = xp; H = W = HX; vec = true; }
    else { plane = py - BATCH * DIM; in = sp; out = spp; H = W = HS; vec = false; }
    int nqx = (W + 3) >> 2, nqy = (H + 3) >> 2;
    int qidx = blockIdx.x * 256 + threadIdx.x;
    if (qidx >= nqx * nqy) return;
    int y0 = (qidx / nqx) << 2, x0 = (qidx % nqx) << 2;
    int c = plane % DIM;
    int HW = H * W;
    float acc[4][4];
    bool fast = dw3_compute(in + (size_t)plane * HW, H, W, w + c * 9,
                            1.0f, bias[c], vec, y0, x0, acc);
    __half* opb = out + (size_t)plane * HW;
    if (fast) {
#pragma unroll
        for (int r = 0; r < 4; r++) {
            uint2 u = {h2pack(acc[r][0], acc[r][1]), h2pack(acc[r][2], acc[r][3])};
            *(uint2*)(opb + (size_t)(y0 + r) * W + x0) = u;
        }
    } else {
#pragma unroll
        for (int r = 0; r < 4; r++) {
            int yo = y0 + r;
            if (yo >= H) break;
#pragma unroll
            for (int j = 0; j < 4; j++) {
                int xo = x0 + j;
                if (xo < W) opb[(size_t)yo * W + xo] = __float2half_rn(acc[r][j]);
            }
        }
    }
}

// ---------------- qkv dw3 uber: fp16 in, fp16 mma-layout out -----------------
__global__ void dw3_qkv_uber(const float* __restrict__ wkvdw,
                             const float* __restrict__ wqdw) {
    int py = blockIdx.y;
    int qidx = blockIdx.x * 256 + threadIdx.x;

    if (py < BATCH * 64) {                       // ---- K pairs ----
        if (qidx >= 62 * 62) return;
        int b = py >> 6, cp = py & 63;
        int y0 = (qidx / 62) << 2, x0 = (qidx % 62) << 2;
        const __half* in0 = g_tkv + ((size_t)(b * 256 + 2 * cp)) * PS_X;
        float a0[4][4], a1[4][4];
        bool fast = dw3_compute_h(in0, HX, HX, wkvdw + (2 * cp) * 9, true, y0, x0, a0);
        dw3_compute_h(in0 + PS_X, HX, HX, wkvdw + (2 * cp + 1) * 9, true, y0, x0, a1);
        uint32_t* op = g_ki + ((size_t)(b * 64 + cp)) * PS_X;
        if (fast) {
#pragma unroll
            for (int r = 0; r < 4; r++) {
                uint4 u = {h2pack(a0[r][0], a1[r][0]), h2pack(a0[r][1], a1[r][1]),
                           h2pack(a0[r][2], a1[r][2]), h2pack(a0[r][3], a1[r][3])};
                *(uint4*)(op + (size_t)(y0 + r) * HX + x0) = u;
            }
        } else {
#pragma unroll
            for (int r = 0; r < 4; r++) {
                int yo = y0 + r;
                if (yo >= HX) break;
#pragma unroll
                for (int j = 0; j < 4; j++) {
                    int xo = x0 + j;
                    if (xo < HX)
                        op[(size_t)yo * HX + xo] = h2pack(a0[r][j], a1[r][j]);
                }
            }
        }
    } else if (py < BATCH * 64 + BATCH * 128) {  // ---- V plain ----
        if (qidx >= 62 * 62) return;
        int p = py - BATCH * 64;
        int b = p >> 7, c = p & 127;
        int y0 = (qidx / 62) << 2, x0 = (qidx % 62) << 2;
        const __half* in = g_tkv + ((size_t)(b * 256 + 128 + c)) * PS_X;
        float a[4][4];
        bool fast = dw3_compute_h(in, HX, HX, wkvdw + (128 + c) * 9, true, y0, x0, a);
        __half* op = g_v + ((size_t)(b * 128 + c)) * PS_X;
        if (fast) {
#pragma unroll
            for (int r = 0; r < 4; r++) {
                uint2 u = {h2pack(a[r][0], a[r][1]), h2pack(a[r][2], a[r][3])};
                *(uint2*)(op + (size_t)(y0 + r) * HX + x0) = u;
            }
        } else {
#pragma unroll
            for (int r = 0; r < 4; r++) {
                int yo = y0 + r;
                if (yo >= HX) break;
#pragma unroll
                for (int j = 0; j < 4; j++) {
                    int xo = x0 + j;
                    if (xo < HX) op[(size_t)yo * HX + xo] = __float2half_rn(a[r][j]);
                }
            }
        }
    } else {                                     // ---- Q pairs ----
        if (qidx >= 16 * 16) return;
        int p = py - BATCH * 64 - BATCH * 128;
        int b = p >> 6, cp = p & 63;
        int y0 = (qidx / 16) << 2, x0 = (qidx % 16) << 2;
        const __half* in0 = g_tq + ((size_t)(b * 128 + 2 * cp)) * PS_S;
        float a0[4][4], a1[4][4];
        dw3_compute_h(in0, HS, HS, wqdw + (2 * cp) * 9, false, y0, x0, a0);
        dw3_compute_h(in0 + PS_S, HS, HS, wqdw + (2 * cp + 1) * 9, false, y0, x0, a1);
        uint32_t* op = g_qi + ((size_t)(b * 64 + cp)) * PS_S;
#pragma unroll
        for (int r = 0; r < 4; r++) {
            int yo = y0 + r;
            if (yo >= HS) break;
#pragma unroll
            for (int j = 0; j < 4; j++) {
                int xo = x0 + j;
                if (xo < HS) op[(size_t)yo * HS + xo] = h2pack(a0[r][j], a1[r][j]);
            }
        }
    }
}

// ---------------- conv1 GEMM body (tf32 mma), templated I/O types ------------
template<typename TI, typename TO>
__device__ __forceinline__ void gemm128_body(
    const float* __restrict__ Wt, const TI* __restrict__ inb,
    TO* __restrict__ outb, int O, int P, int p0, int o0,
    uint32_t (*Ws)[16][136], uint32_t (*Xs)[16][136]) {

    constexpr bool IH = sizeof(TI) == 2;
    constexpr bool OH = sizeof(TO) == 2;

    int tid = threadIdx.x;
    int lane = tid & 31, warp = tid >> 5;
    int wo = warp >> 2;
    int wp = warp & 3;
    int g = lane >> 2;
    int tq = lane & 3;

    float c[4][4][4];
#pragma unroll
    for (int mi = 0; mi < 4; mi++)
#pragma unroll
        for (int ni = 0; ni < 4; ni++)
#pragma unroll
            for (int r = 0; r < 4; r++) c[mi][ni][r] = 0.0f;

    float wr[8], xr[8];

    auto fetch = [&](int kbase) {
#pragma unroll
        for (int l = 0; l < 8; l++) {
            int e = tid + l * 256;
            int k = e >> 7, o = e & 127;
            wr[l] = Wt[(size_t)(kbase + k) * O + o0 + o];
        }
        if (IH) {
#pragma unroll
            for (int l = 0; l < 4; l++) {
                int e2 = tid + l * 256;
                int k = e2 >> 6, o2 = (e2 & 63) * 2;
                int gp = p0 + o2;
                if (gp < P) {
                    __half2 hv = *(const __half2*)((const __half*)inb +
                                                   (size_t)(kbase + k) * P + gp);
                    float2 f = __half22float2(hv);
                    xr[2 * l] = f.x; xr[2 * l + 1] = f.y;
                } else { xr[2 * l] = 0.0f; xr[2 * l + 1] = 0.0f; }
            }
        } else {
#pragma unroll
            for (int l = 0; l < 8; l++) {
                int e = tid + l * 256;
                int k = e >> 7, o = e & 127;
                int gp = p0 + o;
                xr[l] = (gp < P) ? ((const float*)inb)[(size_t)(kbase + k) * P + gp] : 0.0f;
            }
        }
    };
    auto stash = [&](int buf) {
#pragma unroll
        for (int l = 0; l < 8; l++) {
            int e = tid + l * 256;
            int k = e >> 7, o = e & 127;
            Ws[buf][k][o] = f2tf32(wr[l]);
        }
        if (IH) {
#pragma unroll
            for (int l = 0; l < 4; l++) {
                int e2 = tid + l * 256;
                int k = e2 >> 6, o2 = (e2 & 63) * 2;
                Xs[buf][k][o2]     = f2tf32(xr[2 * l]);
                Xs[buf][k][o2 + 1] = f2tf32(xr[2 * l + 1]);
            }
        } else {
#pragma unroll
            for (int l = 0; l < 8; l++) {
                int e = tid + l * 256;
                int k = e >> 7, o = e & 127;
                Xs[buf][k][o] = f2tf32(xr[l]);
            }
        }
    };

    fetch(0);
    stash(0);
    __syncthreads();

    for (int kc = 0; kc < 8; kc++) {
        int cur = kc & 1;
        if (kc < 7) fetch((kc + 1) * 16);
#pragma unroll
        for (int s = 0; s < 2; s++) {
            int kb = s * 8;
            uint32_t bf[4][2];
#pragma unroll
            for (int ni = 0; ni < 4; ni++) {
                int col = wp * 32 + ni * 8 + g;
                bf[ni][0] = Xs[cur][kb + tq][col];
                bf[ni][1] = Xs[cur][kb + tq + 4][col];
            }
            uint32_t af[4][4];
#pragma unroll
            for (int mi = 0; mi < 4; mi++) {
                int row = wo * 64 + mi * 16 + g;
                af[mi][0] = Ws[cur][kb + tq][row];
                af[mi][1] = Ws[cur][kb + tq][row + 8];
                af[mi][2] = Ws[cur][kb + tq + 4][row];
                af[mi][3] = Ws[cur][kb + tq + 4][row + 8];
            }
#pragma unroll
            for (int mi = 0; mi < 4; mi++)
#pragma unroll
                for (int ni = 0; ni < 4; ni++)
                    MMA_TF32(c[mi][ni][0], c[mi][ni][1], c[mi][ni][2], c[mi][ni][3],
                             af[mi][0], af[mi][1], af[mi][2], af[mi][3],
                             bf[ni][0], bf[ni][1]);
        }
        if (kc < 7) stash(cur ^ 1);
        __syncthreads();
    }

#pragma unroll
    for (int mi = 0; mi < 4; mi++) {
        int row0 = o0 + wo * 64 + mi * 16 + g;
#pragma unroll
        for (int ni = 0; ni < 4; ni++) {
            int col = p0 + wp * 32 + ni * 8 + 2 * tq;
            if (col + 1 < P) {
                if (OH) {
                    __half* o0p = (__half*)outb + (size_t)row0 * P + col;
                    __half* o1p = (__half*)outb + (size_t)(row0 + 8) * P + col;
                    *(__half2*)o0p = __floats2half2_rn(c[mi][ni][0], c[mi][ni][1]);
                    *(__half2*)o1p = __floats2half2_rn(c[mi][ni][2], c[mi][ni][3]);
                } else {
                    float* r0 = (float*)outb + (size_t)row0 * P + col;
                    float* r1 = (float*)outb + (size_t)(row0 + 8) * P + col;
                    r0[0] = c[mi][ni][0]; r0[1] = c[mi][ni][1];
                    r1[0] = c[mi][ni][2]; r1[1] = c[mi][ni][3];
                }
            }
        }
    }
}

#define NBLK_KV (481*2*BATCH)   // 1924
#define NBLK_Q  (31*BATCH)      // 62
__global__ __launch_bounds__(256, 2)
void conv1_uber(const float* __restrict__ wkvt, const __half* __restrict__ xp,
                __half* __restrict__ tkv,
                const float* __restrict__ wqt, const __half* __restrict__ spp,
                __half* __restrict__ tq) {
    __shared__ uint32_t Ws[2][16][136];
    __shared__ uint32_t Xs[2][16][136];
    int bid = blockIdx.x;
    if (bid < NBLK_KV) {
        int p0 = (bid % 481) * 128;
        int rest = bid / 481;
        int o0 = (rest & 1) * 128;
        int bz = rest >> 1;
        gemm128_body(wkvt, xp + (size_t)bz * 128 * PS_X,
                     tkv + (size_t)bz * 256 * PS_X, 256, PS_X, p0, o0, Ws, Xs);
    } else {
        int sid = bid - NBLK_KV;
        int p0 = (sid % 31) * 128;
        int bz = sid / 31;
        gemm128_body(wqt, spp + (size_t)bz * 128 * PS_S,
                     tq + (size_t)bz * 128 * PS_S, 128, PS_S, p0, 0, Ws, Xs);
    }
}

__global__ __launch_bounds__(256, 2)
void conv1_single(const float* __restrict__ Wt, const float* __restrict__ in,
                  float* __restrict__ out, int O, int P) {
    __shared__ uint32_t Ws[2][16][136];
    __shared__ uint32_t Xs[2][16][136];
    gemm128_body(Wt, in + (size_t)blockIdx.z * 128 * P,
                 out + (size_t)blockIdx.z * O * P, O, P,
                 blockIdx.x * 128, blockIdx.y * 128, Ws, Xs);
}

// ---------------- windowed attention: fp16 mma, split-K over 2 blocks --------
// blockIdx.z selects KV half (8 chunks each); partials to g_pO/g_pm/g_pl.
__global__ __launch_bounds__(128)
void attn_mma_kernel() {
    __shared__ uint32_t qs[16][72];       // [chpair][qpos]
    __shared__ uint32_t ks[2][16][72];    // [buf][chpair][kvpos]
    __shared__ uint32_t vs[2][32][36];    // [buf][ch][pospair]

    int bn = blockIdx.x;
    int h  = blockIdx.y;
    int z  = blockIdx.z;
    int b = bn / NWIN, n = bn % NWIN;
    int wh = n / 10, ww = n % 10;
    int tid = threadIdx.x, lane = tid & 31, warp = tid >> 5;
    int g = lane >> 2, tq = lane & 3;

    int y0q = 6 * wh, x0q = 6 * ww;
    int y0k = 24 * wh + z * 16;   // this block's 16 KV rows (8 chunks x 2 rows)
    int x0k = 24 * ww;

    const int KSB = 16 * 72;
    const int VSB = 32 * 36;

    const uint32_t* ksrc[2]; uint32_t kdst[2];
#pragma unroll
    for (int t = 0; t < 2; t++) {
        int u = tid + t * 128;
        int cp = u >> 4, rem = u & 15, row = rem >> 3, xq = rem & 7;
        ksrc[t] = g_ki + ((size_t)(b * 64 + h * 16 + cp)) * PS_X
                + (y0k + row) * HX + x0k + xq * 4;
        kdst[t] = (uint32_t)__cvta_generic_to_shared(&ks[0][cp][row * 32 + xq * 4]);
    }
    const uint32_t* vsrc[2]; uint32_t vdst[2];
    const uint32_t* gv32 = (const uint32_t*)g_v;
#pragma unroll
    for (int t = 0; t < 2; t++) {
        int u = tid + t * 128;
        int ch = u >> 3, rem = u & 7, row = rem >> 2, xq = rem & 3;
        vsrc[t] = gv32 + (((size_t)(b * 128 + h * 32 + ch)) * PS_X
                          + (y0k + row) * HX + x0k) / 2 + xq * 4;
        vdst[t] = (uint32_t)__cvta_generic_to_shared(&vs[0][ch][row * 16 + xq * 4]);
    }

#pragma unroll
    for (int t = 0; t < 2; t++) cp16(kdst[t], ksrc[t]);
#pragma unroll
    for (int t = 0; t < 2; t++) cp16(vdst[t], vsrc[t]);
    asm volatile("cp.async.commit_group;" ::: "memory");

    const uint32_t* qsrc = g_qi + ((size_t)(b * 64 + h * 16)) * PS_S;
    for (int e = tid; e < 512; e += 128) {
        int cp = e >> 5, ip = e & 31;
        int i = ip * 2;
        int dy = i >> 3, dx = i & 7;
        uint2 v = *(const uint2*)(qsrc + (size_t)cp * PS_S + (y0q + dy) * HS + x0q + dx);
        qs[cp][i] = v.x;
        qs[cp][i + 1] = v.y;
    }

    float oacc[4][4];
#pragma unroll
    for (int ni = 0; ni < 4; ni++)
#pragma unroll
        for (int r = 0; r < 4; r++) oacc[ni][r] = 0.0f;
    float mrow0 = -1e30f, mrow1 = -1e30f, lrow0 = 0.0f, lrow1 = 0.0f;

    int m0 = warp * 16;

    for (int i = 0; i < 8; i++) {
        int cur = i & 1;
        if (i < 7) {
            int nb = cur ^ 1;
            int koff = (i + 1) * 2 * HX;
            int voff = (i + 1) * HX;
#pragma unroll
            for (int t = 0; t < 2; t++) cp16(kdst[t] + nb * KSB * 4, ksrc[t] + koff);
#pragma unroll
            for (int t = 0; t < 2; t++) cp16(vdst[t] + nb * VSB * 4, vsrc[t] + voff);
            asm volatile("cp.async.commit_group;" ::: "memory");
            asm volatile("cp.async.wait_group 1;" ::: "memory");
        } else {
            asm volatile("cp.async.wait_group 0;" ::: "memory");
        }
        __syncthreads();

        // ---- S = Q K^T (16 x 64 per warp), fp16 mma, log2 domain ----
        float sc[8][4];
#pragma unroll
        for (int ni = 0; ni < 8; ni++)
#pragma unroll
            for (int r = 0; r < 4; r++) sc[ni][r] = 0.0f;

#pragma unroll
        for (int k0 = 0; k0 < 2; k0++) {
            uint32_t a0 = qs[k0 * 8 + tq][m0 + g];
            uint32_t a1 = qs[k0 * 8 + tq][m0 + g + 8];
            uint32_t a2 = qs[k0 * 8 + tq + 4][m0 + g];
            uint32_t a3 = qs[k0 * 8 + tq + 4][m0 + g + 8];
#pragma unroll
            for (int ni = 0; ni < 8; ni++) {
                uint32_t b0 = ks[cur][k0 * 8 + tq][ni * 8 + g];
                uint32_t b1 = ks[cur][k0 * 8 + tq + 4][ni * 8 + g];
                MMA_F16(sc[ni][0], sc[ni][1], sc[ni][2], sc[ni][3],
                        a0, a1, a2, a3, b0, b1);
            }
        }

        // ---- streaming softmax (base-2) ----
        float mx0 = -1e30f, mx1 = -1e30f;
#pragma unroll
        for (int ni = 0; ni < 8; ni++) {
            mx0 = fmaxf(mx0, fmaxf(sc[ni][0], sc[ni][1]));
            mx1 = fmaxf(mx1, fmaxf(sc[ni][2], sc[ni][3]));
        }
#pragma unroll
        for (int off = 1; off <= 2; off <<= 1) {
            mx0 = fmaxf(mx0, __shfl_xor_sync(0xFFFFFFFFu, mx0, off));
            mx1 = fmaxf(mx1, __shfl_xor_sync(0xFFFFFFFFu, mx1, off));
        }
        float mn0 = fmaxf(mrow0, mx0), mn1 = fmaxf(mrow1, mx1);
        float cor0 = ex2(mrow0 - mn0), cor1 = ex2(mrow1 - mn1);
        mrow0 = mn0; mrow1 = mn1;

        float s0 = 0.0f, s1 = 0.0f;
#pragma unroll
        for (int ni = 0; ni < 8; ni++) {
            sc[ni][0] = ex2(sc[ni][0] - mn0);
            sc[ni][1] = ex2(sc[ni][1] - mn0);
            sc[ni][2] = ex2(sc[ni][2] - mn1);
            sc[ni][3] = ex2(sc[ni][3] - mn1);
            s0 += sc[ni][0] + sc[ni][1];
            s1 += sc[ni][2] + sc[ni][3];
        }
#pragma unroll
        for (int off = 1; off <= 2; off <<= 1) {
            s0 += __shfl_xor_sync(0xFFFFFFFFu, s0, off);
            s1 += __shfl_xor_sync(0xFFFFFFFFu, s1, off);
        }
        lrow0 = lrow0 * cor0 + s0;
        lrow1 = lrow1 * cor1 + s1;
#pragma unroll
        for (int ni = 0; ni < 4; ni++) {
            oacc[ni][0] *= cor0; oacc[ni][1] *= cor0;
            oacc[ni][2] *= cor1; oacc[ni][3] *= cor1;
        }

        // ---- O += P V : A-frags are repacked C-frags (NO shuffles) ----
#pragma unroll
        for (int kk = 0; kk < 4; kk++) {
            uint32_t a0 = h2pack(sc[2 * kk][0],     sc[2 * kk][1]);
            uint32_t a1 = h2pack(sc[2 * kk][2],     sc[2 * kk][3]);
            uint32_t a2 = h2pack(sc[2 * kk + 1][0], sc[2 * kk + 1][1]);
            uint32_t a3 = h2pack(sc[2 * kk + 1][2], sc[2 * kk + 1][3]);
#pragma unroll
            for (int ni = 0; ni < 4; ni++) {
                uint32_t b0 = vs[cur][ni * 8 + g][kk * 8 + tq];
                uint32_t b1 = vs[cur][ni * 8 + g][kk * 8 + tq + 4];
                MMA_F16(oacc[ni][0], oacc[ni][1], oacc[ni][2], oacc[ni][3],
                        a0, a1, a2, a3, b0, b1);
            }
        }
        __syncthreads();
    }

    // ---- write partials (unnormalized O + per-row m, l) ----
    size_t pbase = ((size_t)(z * NPART) + bn * 4 + h) * 2048;  // 64*32
    int r0 = m0 + g, r1 = m0 + g + 8;
#pragma unroll
    for (int ni = 0; ni < 4; ni++) {
        int colh = ni * 8 + 2 * tq;
        float* p0 = &g_pO[pbase + (size_t)r0 * 32 + colh];
        float* p1 = &g_pO[pbase + (size_t)r1 * 32 + colh];
        p0[0] = oacc[ni][0]; p0[1] = oacc[ni][1];
        p1[0] = oacc[ni][2]; p1[1] = oacc[ni][3];
    }
    if (tq == 0) {
        int eb = (z * NPART + bn * 4 + h) * 64;
        g_pm[eb + r0] = mrow0; g_pm[eb + r1] = mrow1;
        g_pl[eb + r0] = lrow0; g_pl[eb + r1] = lrow1;
    }
}

// ---------------- combine the two split-K partials into g_win ----------------
__global__ void combine_kernel() {
    int idx = blockIdx.x * 256 + threadIdx.x;
    if (idx >= NPART * 64 * 32) return;
    int row = idx & 63;
    int col = (idx >> 6) & 31;
    int ph  = idx >> 11;          // bn*4 + h
    int e = ph * 64 + row;
    float m0 = g_pm[e], m1 = g_pm[NPART * 64 + e];
    float l0 = g_pl[e], l1 = g_pl[NPART * 64 + e];
    float m = fmaxf(m0, m1);
    float e0 = ex2(m0 - m), e1 = ex2(m1 - m);
    float linv = 1.0f / (l0 * e0 + l1 * e1);
    size_t po = (size_t)ph * 2048 + row * 32 + col;
    float o = (g_pO[po] * e0 + g_pO[(size_t)NPART * 2048 + po] * e1) * linv;
    int bn = ph >> 2, h = ph & 3;
    g_win[((size_t)bn * 128 + h * 32 + col) * 64 + row] = o;
}

// ---------------- reverse (overlap-add with count normalization) -------------
__global__ void reverse_kernel() {
    int idx = blockIdx.x * 256 + threadIdx.x;
    int half = BATCH * DIM * PS_S / 2;
    if (idx >= half + (BATCH * DIM * PS_S & 1)) return;
    int base2 = idx * 2;
    int x = base2 % HS;
    int y = (base2 / HS) % HS;
    int c = (base2 / PS_S) % DIM;
    int b = base2 / (PS_S * DIM);

    float o[2];
#pragma unroll
    for (int t = 0; t < 2; t++) {
        int xx = x + t;
        float s = 0.0f;
        int cnt = 0;
        if (xx < HS) {
            int wlo = max(0, (y - 2) / 6), whi = min(9, y / 6);
            int vlo = max(0, (xx - 2) / 6), vhi = min(9, xx / 6);
            for (int wh = wlo; wh <= whi; wh++) {
                int dy = y - 6 * wh;
                for (int ww = vlo; ww <= vhi; ww++) {
                    int dx = xx - 6 * ww;
                    int n = wh * 10 + ww;
                    s += g_win[((size_t)(b * NWIN + n) * DIM + c) * 64 + dy * 8 + dx];
                }
            }
            cnt = (whi - wlo + 1) * (vhi - vlo + 1);
        }
        o[t] = cnt ? s / (float)cnt : 0.0f;
    }
    float* op = g_acc + (size_t)base2;
    op[0] = o[0];
    if (x + 1 < HS) op[1] = o[1];
}

// ---------------- launch -----------------------------------------------------
extern "C" void kernel_launch(void* const* d_in, const int* in_sizes, int n_in,
                              void* d_out, int out_size) {
    const float* x     = (const float*)d_in[0];
    const float* sp    = (const float*)d_in[1];
    const float* w_pos = (const float*)d_in[2];
    const float* b_pos = (const float*)d_in[3];
    const float* w_q   = (const float*)d_in[4];
    const float* w_qdw = (const float*)d_in[5];
    const float* w_kv  = (const float*)d_in[6];
    const float* w_kvdw= (const float*)d_in[7];
    const float* w_out = (const float*)d_in[8];
    float* out = (float*)d_out;

    __half *xp, *spp, *tkv, *tq;
    float *acc, *wq_t, *wkv_t, *wout_t;
    cudaGetSymbolAddress((void**)&xp,    g_xp);
    cudaGetSymbolAddress((void**)&spp,   g_spp);
    cudaGetSymbolAddress((void**)&tkv,   g_tkv);
    cudaGetSymbolAddress((void**)&tq,    g_tq);
    cudaGetSymbolAddress((void**)&acc,   g_acc);
    cudaGetSymbolAddress((void**)&wq_t,  g_wq_t);
    cudaGetSymbolAddress((void**)&wkv_t, g_wkv_t);
    cudaGetSymbolAddress((void**)&wout_t,g_wout_t);

    // 1/sqrt(32) * log2(e): attention S computed in log2 domain
    const float scale = 0.17677669529663687f * 1.44269504088896340736f;
    transpose_all<<<256, 256>>>(w_q, w_kv, w_out, wq_t, wkv_t, wout_t, scale);

    dw3_pos_uber<<<dim3(16, BATCH*DIM*2), 256>>>(x, xp, sp, spp, w_pos, b_pos);

    conv1_uber<<<NBLK_KV + NBLK_Q, 256>>>(wkv_t, xp, tkv, wq_t, spp, tq);

    dw3_qkv_uber<<<dim3(16, BATCH*64 + BATCH*128 + BATCH*64), 256>>>(w_kvdw, w_qdw);

    attn_mma_kernel<<<dim3(BATCH*NWIN, 4, 2), 128>>>();

    combine_kernel<<<(NPART*64*32 + 255)/256, 256>>>();

    reverse_kernel<<<(BATCH*DIM*PS_S/2 + 255)/256, 256>>>();

    conv1_single<<<dim3((PS_S + 127)/128, 1, BATCH), 256>>>(wout_t, acc, out, DIM, PS_S);
}

// round 15
// speedup vs baseline: 1.2370x; 1.2370x over previous
#include <cuda_runtime.h>
#include <cuda_fp16.h>
#include <cstdint>

#define BATCH 2
#define DIM   128
#define HS    62
#define HX    248
#define PS_S  (HS*HS)   // 3844
#define PS_X  (HX*HX)   // 61504
#define NWIN  100       // 10x10 windows

// ---------------- scratch ----------------------------------------------------
__device__ __half   g_xp  [BATCH*DIM*PS_X];
__device__ __half   g_spp [BATCH*DIM*PS_S];
__device__ __half   g_tkv [BATCH*2*DIM*PS_X];
__device__ __half   g_tq  [BATCH*DIM*PS_S];
__device__ uint32_t g_ki  [BATCH*64*PS_X];      // K fp16, ch-pair interleaved
__device__ __half   g_v   [BATCH*DIM*PS_X];     // V fp16, plain planes
__device__ uint32_t g_qi  [BATCH*64*PS_S];      // Q fp16, ch-pair interleaved
__device__ float    g_win [BATCH*NWIN*DIM*64];
__device__ float    g_acc [BATCH*DIM*PS_S];
__device__ uint32_t g_wq_h  [64*DIM];           // fp16 weights, k-pair packed
__device__ uint32_t g_wkv_h [64*2*DIM];
__device__ uint32_t g_wout_h[64*DIM];

__device__ __forceinline__ float ex2(float x) {
    float y;
    asm("ex2.approx.f32 %0, %1;" : "=f"(y) : "f"(x));
    return y;
}
__device__ __forceinline__ uint32_t h2pack(float lo, float hi) {
    __half2 hh = __floats2half2_rn(lo, hi);
    return *reinterpret_cast<uint32_t*>(&hh);
}

#define MMA_F16(C0,C1,C2,C3,A0,A1,A2,A3,B0,B1)                                \
    asm volatile(                                                             \
        "mma.sync.aligned.m16n8k16.row.col.f32.f16.f16.f32 "                  \
        "{%0,%1,%2,%3}, {%4,%5,%6,%7}, {%8,%9}, {%0,%1,%2,%3};"               \
        : "+f"(C0), "+f"(C1), "+f"(C2), "+f"(C3)                              \
        : "r"(A0), "r"(A1), "r"(A2), "r"(A3), "r"(B0), "r"(B1))

__device__ __forceinline__ void cp16(uint32_t dst, const void* src) {
    asm volatile("cp.async.cg.shared.global [%0], [%1], 16;" :: "r"(dst), "l"(src));
}

// ---------------- weight transpose + fp16 k-pair pack ------------------------
__global__ void transpose_all(const float* __restrict__ wq,
                              const float* __restrict__ wkv,
                              const float* __restrict__ wout,
                              float scale) {
    int idx = blockIdx.x * 256 + threadIdx.x;
    if (idx < 8192) {                    // wq: 64 cpairs x 128 o
        int cp = idx >> 7, o = idx & 127;
        g_wq_h[cp * 128 + o] =
            h2pack(wq[o * 128 + 2 * cp] * scale, wq[o * 128 + 2 * cp + 1] * scale);
    } else if (idx < 8192 + 16384) {     // wkv: 64 cpairs x 256 o
        int i = idx - 8192;
        int cp = i >> 8, o = i & 255;
        g_wkv_h[cp * 256 + o] =
            h2pack(wkv[o * 128 + 2 * cp], wkv[o * 128 + 2 * cp + 1]);
    } else if (idx < 8192 + 16384 + 8192) {
        int i = idx - 8192 - 16384;
        int cp = i >> 7, o = i & 127;
        g_wout_h[cp * 128 + o] =
            h2pack(wout[o * 128 + 2 * cp], wout[o * 128 + 2 * cp + 1]);
    }
}

// ---------------- depthwise 3x3 compute, fp32 input --------------------------
__device__ __forceinline__ bool dw3_compute(const float* __restrict__ ip,
                                            int H, int W,
                                            const float* __restrict__ wc,
                                            float centerAdd, float binit,
                                            bool vec, int y0, int x0,
                                            float acc[4][4]) {
    float w0[3] = {wc[0], wc[3], wc[6]};
    float w1[3] = {wc[1], wc[4] + centerAdd, wc[7]};
    float w2[3] = {wc[2], wc[5], wc[8]};
#pragma unroll
    for (int r = 0; r < 4; r++)
#pragma unroll
        for (int j = 0; j < 4; j++) acc[r][j] = binit;

    bool fast = vec && (x0 >= 4) && (x0 + 8 <= W) && (y0 >= 1) && (y0 + 5 <= H);

    if (fast) {
#pragma unroll
        for (int iy = 0; iy < 6; iy++) {
            const float* rp = ip + (size_t)(y0 + iy - 1) * W;
            float4 mid = *(const float4*)(rp + x0);
            float v[6] = {rp[x0 - 1], mid.x, mid.y, mid.z, mid.w, rp[x0 + 4]};
#pragma unroll
            for (int r = 0; r < 4; r++) {
                int k = iy - r;
                if (k < 0 || k > 2) continue;
                float wy0 = w0[k], wy1 = w1[k], wy2 = w2[k];
#pragma unroll
                for (int j = 0; j < 4; j++)
                    acc[r][j] += v[j] * wy0 + v[j + 1] * wy1 + v[j + 2] * wy2;
            }
        }
    } else {
#pragma unroll
        for (int iy = 0; iy < 6; iy++) {
            int yy = y0 + iy - 1;
            if ((unsigned)yy >= (unsigned)H) continue;
            const float* rp = ip + (size_t)yy * W;
            float v[6];
#pragma unroll
            for (int i = 0; i < 6; i++) {
                int xx = x0 - 1 + i;
                v[i] = ((unsigned)xx < (unsigned)W) ? rp[xx] : 0.0f;
            }
#pragma unroll
            for (int r = 0; r < 4; r++) {
                int k = iy - r;
                if (k < 0 || k > 2) continue;
                float wy0 = w0[k], wy1 = w1[k], wy2 = w2[k];
#pragma unroll
                for (int j = 0; j < 4; j++)
                    acc[r][j] += v[j] * wy0 + v[j + 1] * wy1 + v[j + 2] * wy2;
            }
        }
    }
    return fast;
}

// ---------------- depthwise 3x3 compute, fp16 input --------------------------
__device__ __forceinline__ bool dw3_compute_h(const __half* __restrict__ ip,
                                              int H, int W,
                                              const float* __restrict__ wc,
                                              bool vec, int y0, int x0,
                                              float acc[4][4]) {
    float w0[3] = {wc[0], wc[3], wc[6]};
    float w1[3] = {wc[1], wc[4], wc[7]};
    float w2[3] = {wc[2], wc[5], wc[8]};
#pragma unroll
    for (int r = 0; r < 4; r++)
#pragma unroll
        for (int j = 0; j < 4; j++) acc[r][j] = 0.0f;

    bool fast = vec && (x0 >= 4) && (x0 + 8 <= W) && (y0 >= 1) && (y0 + 5 <= H);

    if (fast) {
#pragma unroll
        for (int iy = 0; iy < 6; iy++) {
            const __half* rp = ip + (size_t)(y0 + iy - 1) * W;
            uint2 m = *(const uint2*)(rp + x0);
            __half2 m01 = *reinterpret_cast<__half2*>(&m.x);
            __half2 m23 = *reinterpret_cast<__half2*>(&m.y);
            float2 f01 = __half22float2(m01);
            float2 f23 = __half22float2(m23);
            float v[6] = {__half2float(rp[x0 - 1]), f01.x, f01.y,
                          f23.x, f23.y, __half2float(rp[x0 + 4])};
#pragma unroll
            for (int r = 0; r < 4; r++) {
                int k = iy - r;
                if (k < 0 || k > 2) continue;
                float wy0 = w0[k], wy1 = w1[k], wy2 = w2[k];
#pragma unroll
                for (int j = 0; j < 4; j++)
                    acc[r][j] += v[j] * wy0 + v[j + 1] * wy1 + v[j + 2] * wy2;
            }
        }
    } else {
#pragma unroll
        for (int iy = 0; iy < 6; iy++) {
            int yy = y0 + iy - 1;
            if ((unsigned)yy >= (unsigned)H) continue;
            const __half* rp = ip + (size_t)yy * W;
            float v[6];
#pragma unroll
            for (int i = 0; i < 6; i++) {
                int xx = x0 - 1 + i;
                v[i] = ((unsigned)xx < (unsigned)W) ? __half2float(rp[xx]) : 0.0f;
            }
#pragma unroll
            for (int r = 0; r < 4; r++) {
                int k = iy - r;
                if (k < 0 || k > 2) continue;
                float wy0 = w0[k], wy1 = w1[k], wy2 = w2[k];
#pragma unroll
                for (int j = 0; j < 4; j++)
                    acc[r][j] += v[j] * wy0 + v[j + 1] * wy1 + v[j + 2] * wy2;
            }
        }
    }
    return fast;
}

// ---------------- pos dw3 uber (fp16 out) ------------------------------------
__global__ void dw3_pos_uber(const float* __restrict__ x, __half* __restrict__ xp,
                             const float* __restrict__ sp, __half* __restrict__ spp,
                             const float* __restrict__ w, const float* __restrict__ bias) {
    int py = blockIdx.y;
    const float* in; __half* out; int H, W; bool vec;
    int plane;
    if (py < BATCH * DIM) { plane = py; in = x; out = xp; H = W = HX; vec = true; }
    else { plane = py - BATCH * DIM; in = sp; out = spp; H = W = HS; vec = false; }
    int nqx = (W + 3) >> 2, nqy = (H + 3) >> 2;
    int qidx = blockIdx.x * 256 + threadIdx.x;
    if (qidx >= nqx * nqy) return;
    int y0 = (qidx / nqx) << 2, x0 = (qidx % nqx) << 2;
    int c = plane % DIM;
    int HW = H * W;
    float acc[4][4];
    bool fast = dw3_compute(in + (size_t)plane * HW, H, W, w + c * 9,
                            1.0f, bias[c], vec, y0, x0, acc);
    __half* opb = out + (size_t)plane * HW;
    if (fast) {
#pragma unroll
        for (int r = 0; r < 4; r++) {
            uint2 u = {h2pack(acc[r][0], acc[r][1]), h2pack(acc[r][2], acc[r][3])};
            *(uint2*)(opb + (size_t)(y0 + r) * W + x0) = u;
        }
    } else {
#pragma unroll
        for (int r = 0; r < 4; r++) {
            int yo = y0 + r;
            if (yo >= H) break;
#pragma unroll
            for (int j = 0; j < 4; j++) {
                int xo = x0 + j;
                if (xo < W) opb[(size_t)yo * W + xo] = __float2half_rn(acc[r][j]);
            }
        }
    }
}

// ---------------- qkv dw3 uber: fp16 in, fp16 mma-layout out -----------------
__global__ void dw3_qkv_uber(const float* __restrict__ wkvdw,
                             const float* __restrict__ wqdw) {
    int py = blockIdx.y;
    int qidx = blockIdx.x * 256 + threadIdx.x;

    if (py < BATCH * 64) {                       // ---- K pairs ----
        if (qidx >= 62 * 62) return;
        int b = py >> 6, cp = py & 63;
        int y0 = (qidx / 62) << 2, x0 = (qidx % 62) << 2;
        const __half* in0 = g_tkv + ((size_t)(b * 256 + 2 * cp)) * PS_X;
        float a0[4][4], a1[4][4];
        bool fast = dw3_compute_h(in0, HX, HX, wkvdw + (2 * cp) * 9, true, y0, x0, a0);
        dw3_compute_h(in0 + PS_X, HX, HX, wkvdw + (2 * cp + 1) * 9, true, y0, x0, a1);
        uint32_t* op = g_ki + ((size_t)(b * 64 + cp)) * PS_X;
        if (fast) {
#pragma unroll
            for (int r = 0; r < 4; r++) {
                uint4 u = {h2pack(a0[r][0], a1[r][0]), h2pack(a0[r][1], a1[r][1]),
                           h2pack(a0[r][2], a1[r][2]), h2pack(a0[r][3], a1[r][3])};
                *(uint4*)(op + (size_t)(y0 + r) * HX + x0) = u;
            }
        } else {
#pragma unroll
            for (int r = 0; r < 4; r++) {
                int yo = y0 + r;
                if (yo >= HX) break;
#pragma unroll
                for (int j = 0; j < 4; j++) {
                    int xo = x0 + j;
                    if (xo < HX)
                        op[(size_t)yo * HX + xo] = h2pack(a0[r][j], a1[r][j]);
                }
            }
        }
    } else if (py < BATCH * 64 + BATCH * 128) {  // ---- V plain ----
        if (qidx >= 62 * 62) return;
        int p = py - BATCH * 64;
        int b = p >> 7, c = p & 127;
        int y0 = (qidx / 62) << 2, x0 = (qidx % 62) << 2;
        const __half* in = g_tkv + ((size_t)(b * 256 + 128 + c)) * PS_X;
        float a[4][4];
        bool fast = dw3_compute_h(in, HX, HX, wkvdw + (128 + c) * 9, true, y0, x0, a);
        __half* op = g_v + ((size_t)(b * 128 + c)) * PS_X;
        if (fast) {
#pragma unroll
            for (int r = 0; r < 4; r++) {
                uint2 u = {h2pack(a[r][0], a[r][1]), h2pack(a[r][2], a[r][3])};
                *(uint2*)(op + (size_t)(y0 + r) * HX + x0) = u;
            }
        } else {
#pragma unroll
            for (int r = 0; r < 4; r++) {
                int yo = y0 + r;
                if (yo >= HX) break;
#pragma unroll
                for (int j = 0; j < 4; j++) {
                    int xo = x0 + j;
                    if (xo < HX) op[(size_t)yo * HX + xo] = __float2half_rn(a[r][j]);
                }
            }
        }
    } else {                                     // ---- Q pairs ----
        if (qidx >= 16 * 16) return;
        int p = py - BATCH * 64 - BATCH * 128;
        int b = p >> 6, cp = p & 63;
        int y0 = (qidx / 16) << 2, x0 = (qidx % 16) << 2;
        const __half* in0 = g_tq + ((size_t)(b * 128 + 2 * cp)) * PS_S;
        float a0[4][4], a1[4][4];
        dw3_compute_h(in0, HS, HS, wqdw + (2 * cp) * 9, false, y0, x0, a0);
        dw3_compute_h(in0 + PS_S, HS, HS, wqdw + (2 * cp + 1) * 9, false, y0, x0, a1);
        uint32_t* op = g_qi + ((size_t)(b * 64 + cp)) * PS_S;
#pragma unroll
        for (int r = 0; r < 4; r++) {
            int yo = y0 + r;
            if (yo >= HS) break;
#pragma unroll
            for (int j = 0; j < 4; j++) {
                int xo = x0 + j;
                if (xo < HS) op[(size_t)yo * HS + xo] = h2pack(a0[r][j], a1[r][j]);
            }
        }
    }
}

// ---------------- conv1 GEMM body (fp16 mma m16n8k16), templated I/O ---------
// Wh global: [64 kpair][O] uint32 (fp16 pairs of adjacent k).
// TI = __half (X already fp16) or float (final conv from g_acc).
template<typename TI, typename TO>
__device__ __forceinline__ void gemm128_f16_body(
    const uint32_t* __restrict__ Whg, const TI* __restrict__ inb,
    TO* __restrict__ outb, int O, int P, int p0, int o0,
    uint32_t (*Wh)[8][136], uint32_t (*Xh)[8][136]) {

    constexpr bool IH = sizeof(TI) == 2;
    constexpr bool OH = sizeof(TO) == 2;

    int tid = threadIdx.x;
    int lane = tid & 31, warp = tid >> 5;
    int wo = warp >> 2;
    int wp = warp & 3;
    int g = lane >> 2;
    int tq = lane & 3;

    float c[4][4][4];
#pragma unroll
    for (int mi = 0; mi < 4; mi++)
#pragma unroll
        for (int ni = 0; ni < 4; ni++)
#pragma unroll
            for (int r = 0; r < 4; r++) c[mi][ni][r] = 0.0f;

    uint32_t wreg[4];
    uint32_t xa[2], xb[2];          // fp16 path: raw row words
    float    fa[2][4];              // fp32 path: raw scalars

    auto fetch = [&](int kp8) {     // kp8 = base kpair of this chunk
#pragma unroll
        for (int l = 0; l < 4; l++) {
            int e = tid + l * 256;
            int kp = e >> 7, o = e & 127;
            wreg[l] = Whg[(size_t)(kp8 + kp) * O + o0 + o];
        }
#pragma unroll
        for (int l = 0; l < 2; l++) {
            int e = tid + l * 256;          // 512 units: 8 kp x 64 ppairs
            int kp = e >> 6, pp = e & 63;
            int k0 = (kp8 + kp) * 2;
            int gp = p0 + 2 * pp;
            if (IH) {
                const uint32_t* r0 = (const uint32_t*)((const __half*)inb + (size_t)k0 * P);
                const uint32_t* r1 = (const uint32_t*)((const __half*)inb + (size_t)(k0 + 1) * P);
                if (gp < P) { xa[l] = r0[gp >> 1]; xb[l] = r1[gp >> 1]; }
                else        { xa[l] = 0u; xb[l] = 0u; }
            } else {
                const float* r0 = (const float*)inb + (size_t)k0 * P;
                const float* r1 = (const float*)inb + (size_t)(k0 + 1) * P;
                if (gp < P) {               // P even, gp even => gp+1 < P
                    fa[l][0] = r0[gp]; fa[l][1] = r0[gp + 1];
                    fa[l][2] = r1[gp]; fa[l][3] = r1[gp + 1];
                } else { fa[l][0] = fa[l][1] = fa[l][2] = fa[l][3] = 0.0f; }
            }
        }
    };
    auto stash = [&](int buf) {
#pragma unroll
        for (int l = 0; l < 4; l++) {
            int e = tid + l * 256;
            int kp = e >> 7, o = e & 127;
            Wh[buf][kp][o] = wreg[l];
        }
#pragma unroll
        for (int l = 0; l < 2; l++) {
            int e = tid + l * 256;
            int kp = e >> 6, pp = e & 63;
            uint32_t w0, w1;
            if (IH) {
                w0 = __byte_perm(xa[l], xb[l], 0x5410);   // {lo(xa), lo(xb)}
                w1 = __byte_perm(xa[l], xb[l], 0x7632);   // {hi(xa), hi(xb)}
            } else {
                w0 = h2pack(fa[l][0], fa[l][2]);
                w1 = h2pack(fa[l][1], fa[l][3]);
            }
            uint2 u = {w0, w1};
            *(uint2*)&Xh[buf][kp][2 * pp] = u;
        }
    };

    fetch(0);
    stash(0);
    __syncthreads();

    for (int kc = 0; kc < 8; kc++) {      // 8 chunks x 8 kpairs = 64 kpairs
        int cur = kc & 1;
        if (kc < 7) fetch((kc + 1) * 8);

        uint32_t bf[4][2];
#pragma unroll
        for (int ni = 0; ni < 4; ni++) {
            int col = wp * 32 + ni * 8 + g;
            bf[ni][0] = Xh[cur][tq][col];
            bf[ni][1] = Xh[cur][tq + 4][col];
        }
        uint32_t af[4][4];
#pragma unroll
        for (int mi = 0; mi < 4; mi++) {
            int row = wo * 64 + mi * 16 + g;
            af[mi][0] = Wh[cur][tq][row];
            af[mi][1] = Wh[cur][tq][row + 8];
            af[mi][2] = Wh[cur][tq + 4][row];
            af[mi][3] = Wh[cur][tq + 4][row + 8];
        }
#pragma unroll
        for (int mi = 0; mi < 4; mi++)
#pragma unroll
            for (int ni = 0; ni < 4; ni++)
                MMA_F16(c[mi][ni][0], c[mi][ni][1], c[mi][ni][2], c[mi][ni][3],
                        af[mi][0], af[mi][1], af[mi][2], af[mi][3],
                        bf[ni][0], bf[ni][1]);

        if (kc < 7) stash(cur ^ 1);
        __syncthreads();
    }

#pragma unroll
    for (int mi = 0; mi < 4; mi++) {
        int row0 = o0 + wo * 64 + mi * 16 + g;
#pragma unroll
        for (int ni = 0; ni < 4; ni++) {
            int col = p0 + wp * 32 + ni * 8 + 2 * tq;
            if (col + 1 < P) {
                if (OH) {
                    __half* o0p = (__half*)outb + (size_t)row0 * P + col;
                    __half* o1p = (__half*)outb + (size_t)(row0 + 8) * P + col;
                    *(__half2*)o0p = __floats2half2_rn(c[mi][ni][0], c[mi][ni][1]);
                    *(__half2*)o1p = __floats2half2_rn(c[mi][ni][2], c[mi][ni][3]);
                } else {
                    float* r0 = (float*)outb + (size_t)row0 * P + col;
                    float* r1 = (float*)outb + (size_t)(row0 + 8) * P + col;
                    r0[0] = c[mi][ni][0]; r0[1] = c[mi][ni][1];
                    r1[0] = c[mi][ni][2]; r1[1] = c[mi][ni][3];
                }
            }
        }
    }
}

#define NBLK_KV (481*2*BATCH)   // 1924
#define NBLK_Q  (31*BATCH)      // 62
__global__ __launch_bounds__(256, 2)
void conv1_uber(const __half* __restrict__ xp, __half* __restrict__ tkv,
                const __half* __restrict__ spp, __half* __restrict__ tq) {
    __shared__ uint32_t Wh[2][8][136];
    __shared__ uint32_t Xh[2][8][136];
    int bid = blockIdx.x;
    if (bid < NBLK_KV) {
        int p0 = (bid % 481) * 128;
        int rest = bid / 481;
        int o0 = (rest & 1) * 128;
        int bz = rest >> 1;
        gemm128_f16_body(g_wkv_h, xp + (size_t)bz * 128 * PS_X,
                         tkv + (size_t)bz * 256 * PS_X, 256, PS_X, p0, o0, Wh, Xh);
    } else {
        int sid = bid - NBLK_KV;
        int p0 = (sid % 31) * 128;
        int bz = sid / 31;
        gemm128_f16_body(g_wq_h, spp + (size_t)bz * 128 * PS_S,
                         tq + (size_t)bz * 128 * PS_S, 128, PS_S, p0, 0, Wh, Xh);
    }
}

__global__ __launch_bounds__(256, 2)
void conv1_single(const float* __restrict__ in, float* __restrict__ out) {
    __shared__ uint32_t Wh[2][8][136];
    __shared__ uint32_t Xh[2][8][136];
    gemm128_f16_body(g_wout_h, in + (size_t)blockIdx.z * 128 * PS_S,
                     out + (size_t)blockIdx.z * 128 * PS_S, 128, PS_S,
                     blockIdx.x * 128, 0, Wh, Xh);
}

// ---------------- windowed attention: fp16 mma (round-11 proven) -------------
__global__ __launch_bounds__(128)
void attn_mma_kernel() {
    __shared__ uint32_t qs[16][72];       // [chpair][qpos]
    __shared__ uint32_t ks[2][16][72];    // [buf][chpair][kvpos]
    __shared__ uint32_t vs[2][32][36];    // [buf][ch][pospair]

    int bn = blockIdx.x;
    int h  = blockIdx.y;
    int b = bn / NWIN, n = bn % NWIN;
    int wh = n / 10, ww = n % 10;
    int tid = threadIdx.x, lane = tid & 31, warp = tid >> 5;
    int g = lane >> 2, tq = lane & 3;

    int y0q = 6 * wh, x0q = 6 * ww;
    int y0k = 24 * wh, x0k = 24 * ww;

    const int KSB = 16 * 72;
    const int VSB = 32 * 36;

    const uint32_t* ksrc[2]; uint32_t kdst[2];
#pragma unroll
    for (int t = 0; t < 2; t++) {
        int u = tid + t * 128;
        int cp = u >> 4, rem = u & 15, row = rem >> 3, xq = rem & 7;
        ksrc[t] = g_ki + ((size_t)(b * 64 + h * 16 + cp)) * PS_X
                + (y0k + row) * HX + x0k + xq * 4;
        kdst[t] = (uint32_t)__cvta_generic_to_shared(&ks[0][cp][row * 32 + xq * 4]);
    }
    const uint32_t* vsrc[2]; uint32_t vdst[2];
    const uint32_t* gv32 = (const uint32_t*)g_v;
#pragma unroll
    for (int t = 0; t < 2; t++) {
        int u = tid + t * 128;
        int ch = u >> 3, rem = u & 7, row = rem >> 2, xq = rem & 3;
        vsrc[t] = gv32 + (((size_t)(b * 128 + h * 32 + ch)) * PS_X
                          + (y0k + row) * HX + x0k) / 2 + xq * 4;
        vdst[t] = (uint32_t)__cvta_generic_to_shared(&vs[0][ch][row * 16 + xq * 4]);
    }

#pragma unroll
    for (int t = 0; t < 2; t++) cp16(kdst[t], ksrc[t]);
#pragma unroll
    for (int t = 0; t < 2; t++) cp16(vdst[t], vsrc[t]);
    asm volatile("cp.async.commit_group;" ::: "memory");

    const uint32_t* qsrc = g_qi + ((size_t)(b * 64 + h * 16)) * PS_S;
    for (int e = tid; e < 512; e += 128) {
        int cp = e >> 5, ip = e & 31;
        int i = ip * 2;
        int dy = i >> 3, dx = i & 7;
        uint2 v = *(const uint2*)(qsrc + (size_t)cp * PS_S + (y0q + dy) * HS + x0q + dx);
        qs[cp][i] = v.x;
        qs[cp][i + 1] = v.y;
    }

    float oacc[4][4];
#pragma unroll
    for (int ni = 0; ni < 4; ni++)
#pragma unroll
        for (int r = 0; r < 4; r++) oacc[ni][r] = 0.0f;
    float mrow0 = -1e30f, mrow1 = -1e30f, lrow0 = 0.0f, lrow1 = 0.0f;

    int m0 = warp * 16;

    for (int i = 0; i < 16; i++) {
        int cur = i & 1;
        if (i < 15) {
            int nb = cur ^ 1;
            int koff = (i + 1) * 2 * HX;
            int voff = (i + 1) * HX;
#pragma unroll
            for (int t = 0; t < 2; t++) cp16(kdst[t] + nb * KSB * 4, ksrc[t] + koff);
#pragma unroll
            for (int t = 0; t < 2; t++) cp16(vdst[t] + nb * VSB * 4, vsrc[t] + voff);
            asm volatile("cp.async.commit_group;" ::: "memory");
            asm volatile("cp.async.wait_group 1;" ::: "memory");
        } else {
            asm volatile("cp.async.wait_group 0;" ::: "memory");
        }
        __syncthreads();

        // ---- S = Q K^T (16 x 64 per warp), fp16 mma, log2 domain ----
        float sc[8][4];
#pragma unroll
        for (int ni = 0; ni < 8; ni++)
#pragma unroll
            for (int r = 0; r < 4; r++) sc[ni][r] = 0.0f;

#pragma unroll
        for (int k0 = 0; k0 < 2; k0++) {
            uint32_t a0 = qs[k0 * 8 + tq][m0 + g];
            uint32_t a1 = qs[k0 * 8 + tq][m0 + g + 8];
            uint32_t a2 = qs[k0 * 8 + tq + 4][m0 + g];
            uint32_t a3 = qs[k0 * 8 + tq + 4][m0 + g + 8];
#pragma unroll
            for (int ni = 0; ni < 8; ni++) {
                uint32_t b0 = ks[cur][k0 * 8 + tq][ni * 8 + g];
                uint32_t b1 = ks[cur][k0 * 8 + tq + 4][ni * 8 + g];
                MMA_F16(sc[ni][0], sc[ni][1], sc[ni][2], sc[ni][3],
                        a0, a1, a2, a3, b0, b1);
            }
        }

        // ---- streaming softmax (base-2) ----
        float mx0 = -1e30f, mx1 = -1e30f;
#pragma unroll
        for (int ni = 0; ni < 8; ni++) {
            mx0 = fmaxf(mx0, fmaxf(sc[ni][0], sc[ni][1]));
            mx1 = fmaxf(mx1, fmaxf(sc[ni][2], sc[ni][3]));
        }
#pragma unroll
        for (int off = 1; off <= 2; off <<= 1) {
            mx0 = fmaxf(mx0, __shfl_xor_sync(0xFFFFFFFFu, mx0, off));
            mx1 = fmaxf(mx1, __shfl_xor_sync(0xFFFFFFFFu, mx1, off));
        }
        float mn0 = fmaxf(mrow0, mx0), mn1 = fmaxf(mrow1, mx1);
        float cor0 = ex2(mrow0 - mn0), cor1 = ex2(mrow1 - mn1);
        mrow0 = mn0; mrow1 = mn1;

        float s0 = 0.0f, s1 = 0.0f;
#pragma unroll
        for (int ni = 0; ni < 8; ni++) {
            sc[ni][0] = ex2(sc[ni][0] - mn0);
            sc[ni][1] = ex2(sc[ni][1] - mn0);
            sc[ni][2] = ex2(sc[ni][2] - mn1);
            sc[ni][3] = ex2(sc[ni][3] - mn1);
            s0 += sc[ni][0] + sc[ni][1];
            s1 += sc[ni][2] + sc[ni][3];
        }
#pragma unroll
        for (int off = 1; off <= 2; off <<= 1) {
            s0 += __shfl_xor_sync(0xFFFFFFFFu, s0, off);
            s1 += __shfl_xor_sync(0xFFFFFFFFu, s1, off);
        }
        lrow0 = lrow0 * cor0 + s0;
        lrow1 = lrow1 * cor1 + s1;
#pragma unroll
        for (int ni = 0; ni < 4; ni++) {
            oacc[ni][0] *= cor0; oacc[ni][1] *= cor0;
            oacc[ni][2] *= cor1; oacc[ni][3] *= cor1;
        }

        // ---- O += P V : A-frags are repacked C-frags (NO shuffles) ----
#pragma unroll
        for (int kk = 0; kk < 4; kk++) {
            uint32_t a0 = h2pack(sc[2 * kk][0],     sc[2 * kk][1]);
            uint32_t a1 = h2pack(sc[2 * kk][2],     sc[2 * kk][3]);
            uint32_t a2 = h2pack(sc[2 * kk + 1][0], sc[2 * kk + 1][1]);
            uint32_t a3 = h2pack(sc[2 * kk + 1][2], sc[2 * kk + 1][3]);
#pragma unroll
            for (int ni = 0; ni < 4; ni++) {
                uint32_t b0 = vs[cur][ni * 8 + g][kk * 8 + tq];
                uint32_t b1 = vs[cur][ni * 8 + g][kk * 8 + tq + 4];
                MMA_F16(oacc[ni][0], oacc[ni][1], oacc[ni][2], oacc[ni][3],
                        a0, a1, a2, a3, b0, b1);
            }
        }
        __syncthreads();
    }

    float inv0 = 1.0f / lrow0, inv1 = 1.0f / lrow1;
#pragma unroll
    for (int ni = 0; ni < 4; ni++) {
        int col = h * 32 + ni * 8 + 2 * tq;
        size_t base = (size_t)bn * DIM;
        g_win[(base + col) * 64 + m0 + g]         = oacc[ni][0] * inv0;
        g_win[(base + col + 1) * 64 + m0 + g]     = oacc[ni][1] * inv0;
        g_win[(base + col) * 64 + m0 + g + 8]     = oacc[ni][2] * inv1;
        g_win[(base + col + 1) * 64 + m0 + g + 8] = oacc[ni][3] * inv1;
    }
}

// ---------------- reverse (overlap-add with count normalization) -------------
__global__ void reverse_kernel() {
    int idx = blockIdx.x * 256 + threadIdx.x;
    int half = BATCH * DIM * PS_S / 2;
    if (idx >= half + (BATCH * DIM * PS_S & 1)) return;
    int base2 = idx * 2;
    int x = base2 % HS;
    int y = (base2 / HS) % HS;
    int c = (base2 / PS_S) % DIM;
    int b = base2 / (PS_S * DIM);

    float o[2];
#pragma unroll
    for (int t = 0; t < 2; t++) {
        int xx = x + t;
        float s = 0.0f;
        int cnt = 0;
        if (xx < HS) {
            int wlo = max(0, (y - 2) / 6), whi = min(9, y / 6);
            int vlo = max(0, (xx - 2) / 6), vhi = min(9, xx / 6);
            for (int wh = wlo; wh <= whi; wh++) {
                int dy = y - 6 * wh;
                for (int ww = vlo; ww <= vhi; ww++) {
                    int dx = xx - 6 * ww;
                    int n = wh * 10 + ww;
                    s += g_win[((size_t)(b * NWIN + n) * DIM + c) * 64 + dy * 8 + dx];
                }
            }
            cnt = (whi - wlo + 1) * (vhi - vlo + 1);
        }
        o[t] = cnt ? s / (float)cnt : 0.0f;
    }
    float* op = g_acc + (size_t)base2;
    op[0] = o[0];
    if (x + 1 < HS) op[1] = o[1];
}

// ---------------- launch -----------------------------------------------------
extern "C" void kernel_launch(void* const* d_in, const int* in_sizes, int n_in,
                              void* d_out, int out_size) {
    const float* x     = (const float*)d_in[0];
    const float* sp    = (const float*)d_in[1];
    const float* w_pos = (const float*)d_in[2];
    const float* b_pos = (const float*)d_in[3];
    const float* w_q   = (const float*)d_in[4];
    const float* w_qdw = (const float*)d_in[5];
    const float* w_kv  = (const float*)d_in[6];
    const float* w_kvdw= (const float*)d_in[7];
    const float* w_out = (const float*)d_in[8];
    float* out = (float*)d_out;

    __half *xp, *spp, *tkv, *tq;
    float *acc;
    cudaGetSymbolAddress((void**)&xp,    g_xp);
    cudaGetSymbolAddress((void**)&spp,   g_spp);
    cudaGetSymbolAddress((void**)&tkv,   g_tkv);
    cudaGetSymbolAddress((void**)&tq,    g_tq);
    cudaGetSymbolAddress((void**)&acc,   g_acc);

    // 1/sqrt(32) * log2(e): attention S computed in log2 domain
    const float scale = 0.17677669529663687f * 1.44269504088896340736f;
    transpose_all<<<128, 256>>>(w_q, w_kv, w_out, scale);

    dw3_pos_uber<<<dim3(16, BATCH*DIM*2), 256>>>(x, xp, sp, spp, w_pos, b_pos);

    conv1_uber<<<NBLK_KV + NBLK_Q, 256>>>(xp, tkv, spp, tq);

    dw3_qkv_uber<<<dim3(16, BATCH*64 + BATCH*128 + BATCH*64), 256>>>(w_kvdw, w_qdw);

    attn_mma_kernel<<<dim3(BATCH*NWIN, 4), 128>>>();

    reverse_kernel<<<(BATCH*DIM*PS_S/2 + 255)/256, 256>>>();

    conv1_single<<<dim3((PS_S + 127)/128, 1, BATCH), 256>>>(acc, out);
}